// round 14
// baseline (speedup 1.0000x reference)
#include <cuda_runtime.h>
#include <cstdint>

// ---------------------------------------------------------------------------
// Compile-time CG instruction table (deterministic, mirrors _build_instructions)
// ---------------------------------------------------------------------------
constexpr int LMAX    = 3;
constexpr int DIM_IN  = 16;   // (LMAX+1)^2
constexpr int NCH     = 64;
constexpr int NC4     = NCH / 4;      // 16 float4 lanes per node
constexpr int MAXNNZ  = 600;

struct Tab {
    int mu1[MAXNNZ];
    int mu2[MAXNNZ];
    int mu3[MAXNNZ];
    int nnz;
    int dim_out;
};

constexpr Tab make_tab() {
    Tab t{};
    int idx = 0;
    int off3 = 0;
    for (int l1 = 0; l1 <= LMAX; ++l1) {
        for (int l2 = 0; l2 <= LMAX; ++l2) {
            int lo = (l1 > l2) ? (l1 - l2) : (l2 - l1);
            int hi = (l1 + l2 < LMAX) ? (l1 + l2) : LMAX;
            for (int l3 = lo; l3 <= hi; ++l3) {
                int k = (2 * l1 + 1 < 2 * l2 + 1) ? (2 * l1 + 1) : (2 * l2 + 1);
                for (int m3 = 0; m3 < 2 * l3 + 1; ++m3) {
                    for (int m1 = 0; m1 < k; ++m1) {
                        int m2 = (m1 + m3) % (2 * l2 + 1);
                        t.mu1[idx] = l1 * l1 + m1;
                        t.mu2[idx] = l2 * l2 + m2;
                        t.mu3[idx] = off3 + m3;
                        ++idx;
                    }
                }
                off3 += 2 * l3 + 1;
            }
        }
    }
    t.nnz = idx;
    t.dim_out = off3;
    return t;
}

// Host copy for constexpr analysis; device copy for in-kernel indexing.
constexpr Tab HTAB = make_tab();
__device__ constexpr Tab TAB = make_tab();

constexpr int NNZ     = 562;
constexpr int DIM_OUT = 156;
static_assert(HTAB.nnz == NNZ, "nnz mismatch");
static_assert(HTAB.dim_out == DIM_OUT, "dim_out mismatch");

// cg coefficients live in constant memory (copied per launch, graph-capturable)
__constant__ float CG_C[NNZ];

// Split point: mu3-segment boundary closest to NNZ/2 (halves write disjoint rows)
constexpr int find_split() {
    int best = 0, bestd = 1 << 30;
    for (int i = 1; i < NNZ; ++i) {
        if (HTAB.mu3[i] != HTAB.mu3[i - 1]) {
            int d = i - NNZ / 2; if (d < 0) d = -d;
            if (d < bestd) { bestd = d; best = i; }
        }
    }
    return best;
}
constexpr int SPLIT = find_split();

// Usage bitmasks, evaluated entirely at host compile time (no device odr-use).
constexpr uint32_t x_mask(int lo, int hi) {
    uint32_t m = 0;
    for (int i = lo; i < hi; ++i) m |= (1u << HTAB.mu1[i]);
    return m;
}
constexpr uint32_t y_quad_mask(int lo, int hi) {
    uint32_t m = 0;
    for (int i = lo; i < hi; ++i) m |= (1u << (HTAB.mu2[i] / 4));
    return m;
}
constexpr uint32_t XM0 = x_mask(0, SPLIT);
constexpr uint32_t XM1 = x_mask(SPLIT, NNZ);
constexpr uint32_t YM0 = y_quad_mask(0, SPLIT);
constexpr uint32_t YM1 = y_quad_mask(SPLIT, NNZ);

// ---------------------------------------------------------------------------
// Per-half worker: fully unrolled over instruction range [LO, HI).
// cg comes from __constant__ at compile-time offsets (uniform LDC path — no
// shared memory, no staging, no __syncthreads). Only loads the x/y components
// the range references (template bitmasks). mu3-sorted segments accumulate in
// 4 fp32 regs, flushed with __stcs.
// ---------------------------------------------------------------------------
template<int LO, int HI, uint32_t XM, uint32_t YM>
__device__ __forceinline__ void run_range(const float4* __restrict__ x4,
                                          const float*  __restrict__ yrow,
                                          float4*       __restrict__ o4)
{
    // y components (vector loads per used quad)
    float ys[DIM_IN];
    const float4* y4 = reinterpret_cast<const float4*>(yrow);
    #pragma unroll
    for (int q = 0; q < 4; ++q) {
        if ((YM >> q) & 1u) {
            float4 v = __ldg(y4 + q);
            ys[4 * q + 0] = v.x;
            ys[4 * q + 1] = v.y;
            ys[4 * q + 2] = v.z;
            ys[4 * q + 3] = v.w;
        }
    }

    // x components used by this range (streaming: read once globally)
    float4 xs[DIM_IN];
    #pragma unroll
    for (int l = 0; l < DIM_IN; ++l)
        if ((XM >> l) & 1u)
            xs[l] = __ldcs(x4 + l * NC4);

    float ax = 0.f, ay = 0.f, az = 0.f, aw = 0.f;

    #pragma unroll
    for (int i = LO; i < HI; ++i) {
        const float  wv = CG_C[i] * ys[TAB.mu2[i]];   // LDC (imm offset) + FMUL
        const float4 v  = xs[TAB.mu1[i]];             // compile-time reg index
        ax = fmaf(wv, v.x, ax);
        ay = fmaf(wv, v.y, ay);
        az = fmaf(wv, v.z, az);
        aw = fmaf(wv, v.w, aw);
        if (i + 1 == HI || TAB.mu3[i + 1] != TAB.mu3[i]) {  // folds at compile time
            float4 r = make_float4(ax, ay, az, aw);
            __stcs(o4 + TAB.mu3[i] * NC4, r);
            ax = ay = az = aw = 0.f;
        }
    }
}

// ---------------------------------------------------------------------------
// Kernel: 128 threads = 4 nodes x 16 float4-lanes x 2 instruction-halves.
// Halves are warp-aligned (threads [0,64) = half 0, [64,128) = half 1):
// no divergence, disjoint output rows. Smaller CTAs (2048 total) halve the
// end-of-kernel wave-tail imbalance vs 1024 CTAs. No smem, no syncthreads.
// ---------------------------------------------------------------------------
constexpr int NPB = 4;              // nodes per block
constexpr int TPB = 2 * NPB * NC4;  // 128 threads

__global__ __launch_bounds__(TPB)
void tp_kernel(const float* __restrict__ x,
               const float* __restrict__ y,
               float*       __restrict__ out)
{
    const int half = threadIdx.x >> 6;      // 0 or 1
    const int t    = threadIdx.x & 63;
    const int nl   = t >> 4;                // node within block
    const int c4   = t & 15;                // float4 lane within channels
    const int node = blockIdx.x * NPB + nl;

    const float4* x4 = reinterpret_cast<const float4*>(x)
                     + (size_t)node * DIM_IN * NC4 + c4;
    const float* yrow = y + (size_t)node * DIM_IN;
    float4* o4 = reinterpret_cast<float4*>(out)
               + (size_t)node * DIM_OUT * NC4 + c4;

    if (half == 0)
        run_range<0, SPLIT, XM0, YM0>(x4, yrow, o4);
    else
        run_range<SPLIT, NNZ, XM1, YM1>(x4, yrow, o4);
}

// ---------------------------------------------------------------------------
// Launch: inputs per setup_inputs order: x, y, cg_coeffs, mu_1, mu_2, mu_3, ...
// cg (2.2 KB) is copied into __constant__ via an async D2D memcpy — a valid
// graph node, same work on every call.
// ---------------------------------------------------------------------------
extern "C" void kernel_launch(void* const* d_in, const int* in_sizes, int n_in,
                              void* d_out, int out_size)
{
    const float* x   = (const float*)d_in[0];
    const float* y   = (const float*)d_in[1];
    const float* cg  = (const float*)d_in[2];
    float*       out = (float*)d_out;

    cudaMemcpyToSymbolAsync(CG_C, cg, NNZ * sizeof(float), 0,
                            cudaMemcpyDeviceToDevice, 0);

    const int n_nodes = in_sizes[1] / DIM_IN;   // y has [N, 16]
    const int grid    = n_nodes / NPB;          // 8192 / 4 = 2048

    tp_kernel<<<grid, TPB>>>(x, y, out);
}

// round 16
// speedup vs baseline: 1.2935x; 1.2935x over previous
#include <cuda_runtime.h>
#include <cstdint>

// ---------------------------------------------------------------------------
// Compile-time CG instruction table (deterministic, mirrors _build_instructions)
// ---------------------------------------------------------------------------
constexpr int LMAX    = 3;
constexpr int DIM_IN  = 16;   // (LMAX+1)^2
constexpr int NCH     = 64;
constexpr int NC4     = NCH / 4;      // 16 float4 lanes per node
constexpr int MAXNNZ  = 600;

struct Tab {
    int mu1[MAXNNZ];
    int mu2[MAXNNZ];
    int mu3[MAXNNZ];
    int nnz;
    int dim_out;
};

constexpr Tab make_tab() {
    Tab t{};
    int idx = 0;
    int off3 = 0;
    for (int l1 = 0; l1 <= LMAX; ++l1) {
        for (int l2 = 0; l2 <= LMAX; ++l2) {
            int lo = (l1 > l2) ? (l1 - l2) : (l2 - l1);
            int hi = (l1 + l2 < LMAX) ? (l1 + l2) : LMAX;
            for (int l3 = lo; l3 <= hi; ++l3) {
                int k = (2 * l1 + 1 < 2 * l2 + 1) ? (2 * l1 + 1) : (2 * l2 + 1);
                for (int m3 = 0; m3 < 2 * l3 + 1; ++m3) {
                    for (int m1 = 0; m1 < k; ++m1) {
                        int m2 = (m1 + m3) % (2 * l2 + 1);
                        t.mu1[idx] = l1 * l1 + m1;
                        t.mu2[idx] = l2 * l2 + m2;
                        t.mu3[idx] = off3 + m3;
                        ++idx;
                    }
                }
                off3 += 2 * l3 + 1;
            }
        }
    }
    t.nnz = idx;
    t.dim_out = off3;
    return t;
}

// Host copy for constexpr analysis; device copy for in-kernel indexing.
constexpr Tab HTAB = make_tab();
__device__ constexpr Tab TAB = make_tab();

constexpr int NNZ     = 562;
constexpr int DIM_OUT = 156;
constexpr int NNZ4    = (NNZ + 3) / 4;   // 141 float4 groups
constexpr int NNZPAD  = NNZ4 * 4;        // 564 (padded so group loads stay in-bounds)
static_assert(HTAB.nnz == NNZ, "nnz mismatch");
static_assert(HTAB.dim_out == DIM_OUT, "dim_out mismatch");

// Split point: mu3-segment boundary closest to NNZ/2 (halves write disjoint rows)
constexpr int find_split() {
    int best = 0, bestd = 1 << 30;
    for (int i = 1; i < NNZ; ++i) {
        if (HTAB.mu3[i] != HTAB.mu3[i - 1]) {
            int d = i - NNZ / 2; if (d < 0) d = -d;
            if (d < bestd) { bestd = d; best = i; }
        }
    }
    return best;
}
constexpr int SPLIT = find_split();

// Usage bitmasks, evaluated entirely at host compile time (no device odr-use).
constexpr uint32_t x_mask(int lo, int hi) {
    uint32_t m = 0;
    for (int i = lo; i < hi; ++i) m |= (1u << HTAB.mu1[i]);
    return m;
}
constexpr uint32_t y_quad_mask(int lo, int hi) {
    uint32_t m = 0;
    for (int i = lo; i < hi; ++i) m |= (1u << (HTAB.mu2[i] / 4));
    return m;
}
constexpr uint32_t XM0 = x_mask(0, SPLIT);
constexpr uint32_t XM1 = x_mask(SPLIT, NNZ);
constexpr uint32_t YM0 = y_quad_mask(0, SPLIT);
constexpr uint32_t YM1 = y_quad_mask(SPLIT, NNZ);

// ---------------------------------------------------------------------------
// Per-half worker: fully unrolled over instruction range [LO, HI).
// cg read from shared via aligned float4 groups (LDS.128 broadcast). Only
// loads the x/y components the range references (template bitmasks).
// x loaded with default caching (__ldg): each float4 is read by BOTH halves,
// so the second read should hit L1/L2 instead of re-streaming from DRAM.
// mu3-sorted segments accumulate in 4 fp32 regs, flushed with __stcs.
// ---------------------------------------------------------------------------
template<int LO, int HI, uint32_t XM, uint32_t YM>
__device__ __forceinline__ void run_range(const float4* __restrict__ x4,
                                          const float*  __restrict__ yrow,
                                          const float4* __restrict__ cg_s4,
                                          float4*       __restrict__ o4)
{
    // y components (vector loads per used quad)
    float ys[DIM_IN];
    const float4* y4 = reinterpret_cast<const float4*>(yrow);
    #pragma unroll
    for (int q = 0; q < 4; ++q) {
        if ((YM >> q) & 1u) {
            float4 v = __ldg(y4 + q);
            ys[4 * q + 0] = v.x;
            ys[4 * q + 1] = v.y;
            ys[4 * q + 2] = v.z;
            ys[4 * q + 3] = v.w;
        }
    }

    // x components used by this range (cached: re-read by the other half)
    float4 xs[DIM_IN];
    #pragma unroll
    for (int l = 0; l < DIM_IN; ++l)
        if ((XM >> l) & 1u)
            xs[l] = __ldg(x4 + l * NC4);

    float ax = 0.f, ay = 0.f, az = 0.f, aw = 0.f;

    constexpr int G0 = LO / 4;            // first group touching [LO,HI)
    constexpr int G1 = (HI + 3) / 4;      // one past last group

    #pragma unroll
    for (int g = G0; g < G1; ++g) {
        const float4 c4v = cg_s4[g];      // broadcast LDS.128 (1 address/warp)
        const float cv[4] = { c4v.x, c4v.y, c4v.z, c4v.w };
        #pragma unroll
        for (int j = 0; j < 4; ++j) {
            const int i = 4 * g + j;      // compile-time under full unroll
            if (i >= LO && i < HI) {
                const float  wv = cv[j] * ys[TAB.mu2[i]];
                const float4 v  = xs[TAB.mu1[i]];   // compile-time reg index
                ax = fmaf(wv, v.x, ax);
                ay = fmaf(wv, v.y, ay);
                az = fmaf(wv, v.z, az);
                aw = fmaf(wv, v.w, aw);
                if (i + 1 == HI || TAB.mu3[i + 1] != TAB.mu3[i]) {  // folds
                    float4 r = make_float4(ax, ay, az, aw);
                    __stcs(o4 + TAB.mu3[i] * NC4, r);
                    ax = ay = az = aw = 0.f;
                }
            }
        }
    }
}

// ---------------------------------------------------------------------------
// Kernel: 256 threads = 8 nodes x 16 float4-lanes x 2 instruction-halves.
// Halves are warp-aligned (threads [0,128) = half 0, [128,256) = half 1):
// no divergence, disjoint output rows. No reg cap (occupancy proven
// non-binding across R7/R8); kernel sits on the HBM write plateau.
// ---------------------------------------------------------------------------
constexpr int NPB = 8;              // nodes per block
constexpr int TPB = 2 * NPB * NC4;  // 256 threads

__global__ __launch_bounds__(TPB)
void tp_kernel(const float* __restrict__ x,
               const float* __restrict__ y,
               const float* __restrict__ cg,
               float*       __restrict__ out)
{
    __shared__ float4 cg_s4[NNZ4];

    // Stage cg into shared (zero-pad tail)
    for (int t = threadIdx.x; t < NNZPAD; t += TPB)
        reinterpret_cast<float*>(cg_s4)[t] = (t < NNZ) ? __ldg(&cg[t]) : 0.f;
    __syncthreads();

    const int half = threadIdx.x >> 7;      // 0 or 1
    const int t    = threadIdx.x & 127;
    const int nl   = t >> 4;                // node within block
    const int c4   = t & 15;                // float4 lane within channels
    const int node = blockIdx.x * NPB + nl;

    const float4* x4 = reinterpret_cast<const float4*>(x)
                     + (size_t)node * DIM_IN * NC4 + c4;
    const float* yrow = y + (size_t)node * DIM_IN;
    float4* o4 = reinterpret_cast<float4*>(out)
               + (size_t)node * DIM_OUT * NC4 + c4;

    if (half == 0)
        run_range<0, SPLIT, XM0, YM0>(x4, yrow, cg_s4, o4);
    else
        run_range<SPLIT, NNZ, XM1, YM1>(x4, yrow, cg_s4, o4);
}

// ---------------------------------------------------------------------------
// Launch: inputs per setup_inputs order: x, y, cg_coeffs, mu_1, mu_2, mu_3, ...
// ---------------------------------------------------------------------------
extern "C" void kernel_launch(void* const* d_in, const int* in_sizes, int n_in,
                              void* d_out, int out_size)
{
    const float* x   = (const float*)d_in[0];
    const float* y   = (const float*)d_in[1];
    const float* cg  = (const float*)d_in[2];
    float*       out = (float*)d_out;

    const int n_nodes = in_sizes[1] / DIM_IN;   // y has [N, 16]
    const int grid    = n_nodes / NPB;          // 8192 / 8 = 1024

    tp_kernel<<<grid, TPB>>>(x, y, cg, out);
}